// round 5
// baseline (speedup 1.0000x reference)
#include <cuda_runtime.h>
#include <math.h>

#define EMBED   2048
#define NEXP    64
#define TOPK    8
#define KC      16                 // K-chunk
#define NCHUNK  (EMBED / KC)       // 128
#define TPB     64                 // threads per CTA (2 warps), 1 token/thread
#define TOKS    64                 // tokens per CTA
#define NBLK    512

typedef unsigned long long u64;

__device__ float        g_wt[EMBED * NEXP];   // W transposed: [k][e]
__device__ float        g_pi_part[NBLK][NEXP];
__device__ unsigned int g_cnt[NEXP];

// One-shot per launch: transpose W into g_wt, zero counters.
__global__ void prep_kernel(const float* __restrict__ w) {
    int idx = blockIdx.x * blockDim.x + threadIdx.x;   // e*2048 + k
    int e = idx >> 11, k = idx & 2047;
    g_wt[k * NEXP + e] = w[idx];
    if (idx < NEXP) g_cnt[idx] = 0u;
}

__device__ __forceinline__ u64 ffma2(u64 a, u64 b, u64 c) {
    u64 d;
    asm("fma.rn.f32x2 %0, %1, %2, %3;" : "=l"(d) : "l"(a), "l"(b), "l"(c));
    return d;
}
__device__ __forceinline__ u64 pack2(float f) {
    u64 d;
    asm("mov.b64 %0, {%1, %1};" : "=l"(d) : "f"(f));
    return d;
}
__device__ __forceinline__ void lds_v2(u64& a, u64& b, unsigned addr) {
    asm volatile("ld.shared.v2.b64 {%0, %1}, [%2];" : "=l"(a), "=l"(b) : "r"(addr));
}
__device__ __forceinline__ void cp_async16(unsigned saddr, const void* gaddr) {
    asm volatile("cp.async.ca.shared.global [%0], [%1], 16;" :: "r"(saddr), "l"(gaddr));
}
__device__ __forceinline__ void cp_commit() { asm volatile("cp.async.commit_group;"); }
__device__ __forceinline__ void cp_wait1()  { asm volatile("cp.async.wait_group 1;" ::: "memory"); }
__device__ __forceinline__ void cp_wait0()  { asm volatile("cp.async.wait_group 0;" ::: "memory"); }

__device__ __forceinline__ void load16(float (&d)[16], const float* p) {
    #pragma unroll
    for (int i = 0; i < 4; i++) {
        float4 v = *(const float4*)(p + i * 4);
        d[i * 4 + 0] = v.x; d[i * 4 + 1] = v.y; d[i * 4 + 2] = v.z; d[i * 4 + 3] = v.w;
    }
}

// Round-4-identical softmax numerics: sequential-k logits in `a`
// (lo lane = even expert, hi = odd), expf, butterfly sum (16..1), IEEE div.
__device__ __forceinline__ void softmax_row(const u64 (&a)[32], float (&p)[NEXP]) {
    float l[NEXP];
    #pragma unroll
    for (int m = 0; m < 32; m++) {
        unsigned lo, hi;
        asm("mov.b64 {%0, %1}, %2;" : "=r"(lo), "=r"(hi) : "l"(a[m]));
        l[2 * m]     = __uint_as_float(lo);
        l[2 * m + 1] = __uint_as_float(hi);
    }
    float mx = l[0];
    #pragma unroll
    for (int e = 1; e < NEXP; e++) mx = fmaxf(mx, l[e]);
    float ex[NEXP];
    #pragma unroll
    for (int e = 0; e < NEXP; e++) ex[e] = expf(l[e] - mx);
    float v[32];
    #pragma unroll
    for (int j = 0; j < 32; j++) v[j] = ex[j] + ex[j + 32];
    #pragma unroll
    for (int off = 16; off >= 1; off >>= 1) {
        float nv[32];
        #pragma unroll
        for (int j = 0; j < 32; j++) nv[j] = v[j] + v[j ^ off];
        #pragma unroll
        for (int j = 0; j < 32; j++) v[j] = nv[j];
    }
    float s = v[0];
    #pragma unroll
    for (int e = 0; e < NEXP; e++) p[e] = ex[e] / s;
}

__global__ void __launch_bounds__(TPB) gate_kernel(
    const float* __restrict__ x, float* __restrict__ out, int ntok)
{
    __shared__ __align__(16) float wbuf[3][KC * NEXP];   // 3 x 4KB Wt ring
    __shared__ float Ls[TOKS][NEXP + 1];
    __shared__ unsigned int cntS[NEXP];

    const int t = threadIdx.x;                 // 0..63, one token per thread
    const long tok = (long)blockIdx.x * TOKS + t;
    const float* xr = x + tok * EMBED;
    cntS[t] = 0u;

    u64 acc[32];
    #pragma unroll
    for (int m = 0; m < 32; m++) acc[m] = 0ULL;

    const unsigned wb0 = (unsigned)__cvta_generic_to_shared(&wbuf[0][0]);

    // stage Wt chunk 0 into ring slot 0 (contiguous 4KB, 64 threads x 4 x 16B)
    #pragma unroll
    for (int j = 0; j < 4; j++) {
        int f = t + j * TPB;
        cp_async16(wb0 + f * 16, g_wt + f * 4);
    }
    cp_commit();

    float xa[16], xn[16];
    load16(xa, xr);

    int rd = 0, wr = 1;   // ring slots
    for (int c = 0; c < NCHUNK; c++) {
        if (c + 1 < NCHUNK) {
            unsigned dst = wb0 + wr * (KC * NEXP * 4);
            const float* src = g_wt + (c + 1) * (KC * NEXP);
            #pragma unroll
            for (int j = 0; j < 4; j++) {
                int f = t + j * TPB;
                cp_async16(dst + f * 16, src + f * 4);
            }
            cp_commit();
            load16(xn, xr + (c + 1) * KC);
            cp_wait1();
        } else {
            cp_wait0();
        }
        __syncthreads();

        const unsigned base = wb0 + rd * (KC * NEXP * 4);
        #pragma unroll
        for (int k = 0; k < KC; k++) {
            u64 a = pack2(xa[k]);
            #pragma unroll
            for (int m = 0; m < 8; m++) {
                u64 b0, b1, b2, b3;
                unsigned ad = base + k * (NEXP * 4) + m * 32;
                lds_v2(b0, b1, ad);
                lds_v2(b2, b3, ad + 16);
                acc[4 * m + 0] = ffma2(a, b0, acc[4 * m + 0]);
                acc[4 * m + 1] = ffma2(a, b1, acc[4 * m + 1]);
                acc[4 * m + 2] = ffma2(a, b2, acc[4 * m + 2]);
                acc[4 * m + 3] = ffma2(a, b3, acc[4 * m + 3]);
            }
        }
        if (c + 1 < NCHUNK) {
            #pragma unroll
            for (int i = 0; i < 16; i++) xa[i] = xn[i];
        }
        rd = (rd + 1) % 3; wr = (wr + 1) % 3;
    }

    // ---------------- epilogue ----------------
    {
        float p[NEXP];
        softmax_row(acc, p);
        #pragma unroll
        for (int e = 0; e < NEXP; e++) Ls[t][e] = p[e];
    }
    __syncthreads();

    // per-CTA Pi partials (ascending r: bitwise-identical to prior rounds)
    {
        float s1 = 0.f;
        #pragma unroll
        for (int r = 0; r < TOKS; r++) s1 += Ls[r][t];
        g_pi_part[blockIdx.x][t] = s1;
    }
    __syncthreads();   // Pi reads done before top-k mutates Ls

    // top-8: ascending scan, strict > => lowest index wins ties
    #pragma unroll 1
    for (int kk = 0; kk < TOPK; kk++) {
        float best = -1.f; int bi = 0;
        #pragma unroll
        for (int e = 0; e < NEXP; e++) {
            float v = Ls[t][e];
            if (v > best) { best = v; bi = e; }
        }
        Ls[t][bi] = -1.f;
        out[tok * TOPK + kk] = (float)bi;
        out[(long)ntok * TOPK + tok * TOPK + kk] = best;
        atomicAdd(&cntS[bi], 1u);
    }
    __syncthreads();
    if (cntS[t]) atomicAdd(&g_cnt[t], cntS[t]);
}

__global__ void finalize_kernel(float* __restrict__ aux, int nblocks, float ntokf) {
    int e = threadIdx.x;   // 64 threads
    float s = 0.f;
    for (int b = 0; b < nblocks; b++) s += g_pi_part[b][e];
    float Pi = s / ntokf;
    float ce = (float)g_cnt[e] / (ntokf * (float)TOPK);
    float v = Pi * ce * (float)NEXP;
    __shared__ float red[2];
    #pragma unroll
    for (int off = 16; off; off >>= 1)
        v += __shfl_xor_sync(0xffffffffu, v, off);
    if ((e & 31) == 0) red[e >> 5] = v;
    __syncthreads();
    if (e == 0) aux[0] = (red[0] + red[1]) * 0.01f;
}

extern "C" void kernel_launch(void* const* d_in, const int* in_sizes, int n_in,
                              void* d_out, int out_size) {
    const float* x = (const float*)d_in[0];
    const float* w = (const float*)d_in[1];
    float* out = (float*)d_out;
    int ntok = in_sizes[0] / EMBED;        // 32768
    int nblocks = ntok / TOKS;             // 512
    prep_kernel<<<(NEXP * EMBED) / 256, 256>>>(w);
    gate_kernel<<<nblocks, TPB>>>(x, out, ntok);
    finalize_kernel<<<1, 64>>>(out + (long)ntok * 2 * TOPK, nblocks, (float)ntok);
}

// round 6
// speedup vs baseline: 1.0824x; 1.0824x over previous
#include <cuda_runtime.h>
#include <math.h>

#define EMBED   2048
#define NEXP    64
#define TOPK    8
#define KC      16                 // K-chunk
#define NCHUNK  (EMBED / KC)       // 128
#define TPB     64                 // 2 warps: warp = expert half, thread = 2 tokens
#define TOKS    64                 // tokens per CTA
#define NBLK    512

typedef unsigned long long u64;

__device__ float        g_wt[EMBED * NEXP];   // W transposed: [k][e]
__device__ float        g_pi_part[NBLK][NEXP];
__device__ unsigned int g_cnt[NEXP];

// One-shot per launch: transpose W into g_wt, zero counters.
__global__ void prep_kernel(const float* __restrict__ w) {
    int idx = blockIdx.x * blockDim.x + threadIdx.x;   // e*2048 + k
    int e = idx >> 11, k = idx & 2047;
    g_wt[k * NEXP + e] = w[idx];
    if (idx < NEXP) g_cnt[idx] = 0u;
}

__device__ __forceinline__ u64 ffma2(u64 a, u64 b, u64 c) {
    u64 d;
    asm("fma.rn.f32x2 %0, %1, %2, %3;" : "=l"(d) : "l"(a), "l"(b), "l"(c));
    return d;
}
__device__ __forceinline__ u64 pack2(float f) {
    u64 d;
    asm("mov.b64 %0, {%1, %1};" : "=l"(d) : "f"(f));
    return d;
}
__device__ __forceinline__ void lds_v2(u64& a, u64& b, unsigned addr) {
    asm volatile("ld.shared.v2.b64 {%0, %1}, [%2];" : "=l"(a), "=l"(b) : "r"(addr));
}
__device__ __forceinline__ void cp_async16(unsigned saddr, const void* gaddr) {
    asm volatile("cp.async.ca.shared.global [%0], [%1], 16;" :: "r"(saddr), "l"(gaddr));
}
__device__ __forceinline__ void cp_commit() { asm volatile("cp.async.commit_group;"); }
__device__ __forceinline__ void cp_wait1()  { asm volatile("cp.async.wait_group 1;" ::: "memory"); }
__device__ __forceinline__ void cp_wait0()  { asm volatile("cp.async.wait_group 0;" ::: "memory"); }

__device__ __forceinline__ void load16(float (&d)[16], const float* p) {
    #pragma unroll
    for (int i = 0; i < 4; i++) {
        float4 v = *(const float4*)(p + i * 4);
        d[i * 4 + 0] = v.x; d[i * 4 + 1] = v.y; d[i * 4 + 2] = v.z; d[i * 4 + 3] = v.w;
    }
}

__global__ void __launch_bounds__(TPB) gate_kernel(
    const float* __restrict__ x, float* __restrict__ out, int ntok)
{
    __shared__ __align__(16) float wbuf[3][KC * NEXP];   // 3 x 4KB Wt ring
    __shared__ float Ls[TOKS][NEXP + 1];
    __shared__ unsigned int cntS[NEXP];

    const int t   = threadIdx.x;          // 0..63
    const int l   = t & 31;               // lane
    const int wid = t >> 5;               // 0/1 = expert half
    const int e0  = wid * 32;             // this warp's expert base
    const long tokA = (long)blockIdx.x * TOKS + 2 * l;   // tokens 2l, 2l+1
    const float* xr0 = x + tokA * EMBED;
    const float* xr1 = xr0 + EMBED;
    cntS[t] = 0u;

    u64 acc0[16], acc1[16];               // 16 expert-pairs x 2 tokens
    #pragma unroll
    for (int m = 0; m < 16; m++) { acc0[m] = 0ULL; acc1[m] = 0ULL; }

    const unsigned wb0 = (unsigned)__cvta_generic_to_shared(&wbuf[0][0]);

    // stage Wt chunk 0 into ring slot 0 (64 threads x 4 x 16B = 4KB)
    #pragma unroll
    for (int j = 0; j < 4; j++) {
        int f = t + j * TPB;
        cp_async16(wb0 + f * 16, g_wt + f * 4);
    }
    cp_commit();

    float xa0[16], xa1[16], xn0[16], xn1[16];
    load16(xa0, xr0); load16(xa1, xr1);

    int rd = 0, wr = 1;
    for (int c = 0; c < NCHUNK; c++) {
        if (c + 1 < NCHUNK) {
            unsigned dst = wb0 + wr * (KC * NEXP * 4);
            const float* src = g_wt + (c + 1) * (KC * NEXP);
            #pragma unroll
            for (int j = 0; j < 4; j++) {
                int f = t + j * TPB;
                cp_async16(dst + f * 16, src + f * 4);
            }
            cp_commit();
            load16(xn0, xr0 + (c + 1) * KC);
            load16(xn1, xr1 + (c + 1) * KC);
            cp_wait1();
        } else {
            cp_wait0();
        }
        __syncthreads();

        const unsigned base = wb0 + rd * (KC * NEXP * 4) + e0 * 4;
        #pragma unroll
        for (int k = 0; k < KC; k++) {
            u64 a0 = pack2(xa0[k]);
            u64 a1 = pack2(xa1[k]);
            #pragma unroll
            for (int m = 0; m < 8; m++) {
                u64 b0, b1;
                lds_v2(b0, b1, base + k * (NEXP * 4) + m * 16);
                acc0[2 * m]     = ffma2(a0, b0, acc0[2 * m]);
                acc0[2 * m + 1] = ffma2(a0, b1, acc0[2 * m + 1]);
                acc1[2 * m]     = ffma2(a1, b0, acc1[2 * m]);
                acc1[2 * m + 1] = ffma2(a1, b1, acc1[2 * m + 1]);
            }
        }
        if (c + 1 < NCHUNK) {
            #pragma unroll
            for (int i = 0; i < 16; i++) {
                xa0[i] = xn0[i]; xa1[i] = xn1[i];
            }
        }
        rd = (rd + 1) % 3; wr = (wr + 1) % 3;
    }

    // ---- logits -> smem (unpack; bitwise same values as register path) ----
    #pragma unroll
    for (int m = 0; m < 16; m++) {
        unsigned lo, hi;
        asm("mov.b64 {%0, %1}, %2;" : "=r"(lo), "=r"(hi) : "l"(acc0[m]));
        Ls[2 * l][e0 + 2 * m]     = __uint_as_float(lo);
        Ls[2 * l][e0 + 2 * m + 1] = __uint_as_float(hi);
        asm("mov.b64 {%0, %1}, %2;" : "=r"(lo), "=r"(hi) : "l"(acc1[m]));
        Ls[2 * l + 1][e0 + 2 * m]     = __uint_as_float(lo);
        Ls[2 * l + 1][e0 + 2 * m + 1] = __uint_as_float(hi);
    }
    __syncthreads();

    // ---- softmax: thread t -> token t; numerics identical to round 4/5 ----
    {
        float lg[NEXP];
        #pragma unroll
        for (int e = 0; e < NEXP; e++) lg[e] = Ls[t][e];
        float mx = lg[0];
        #pragma unroll
        for (int e = 1; e < NEXP; e++) mx = fmaxf(mx, lg[e]);
        float ex[NEXP];
        #pragma unroll
        for (int e = 0; e < NEXP; e++) ex[e] = expf(lg[e] - mx);
        float v[32];
        #pragma unroll
        for (int j = 0; j < 32; j++) v[j] = ex[j] + ex[j + 32];
        #pragma unroll
        for (int off = 16; off >= 1; off >>= 1) {
            float nv[32];
            #pragma unroll
            for (int j = 0; j < 32; j++) nv[j] = v[j] + v[j ^ off];
            #pragma unroll
            for (int j = 0; j < 32; j++) v[j] = nv[j];
        }
        float s = v[0];
        __syncthreads();   // all logit reads done before overwrite
        #pragma unroll
        for (int e = 0; e < NEXP; e++) Ls[t][e] = ex[e] / s;
    }
    __syncthreads();

    // per-CTA Pi partials (ascending r: bitwise-identical)
    {
        float s1 = 0.f;
        #pragma unroll
        for (int r = 0; r < TOKS; r++) s1 += Ls[r][t];
        g_pi_part[blockIdx.x][t] = s1;
    }
    __syncthreads();

    // top-8: ascending scan, strict > => lowest index wins ties
    const long tok = (long)blockIdx.x * TOKS + t;
    #pragma unroll 1
    for (int kk = 0; kk < TOPK; kk++) {
        float best = -1.f; int bi = 0;
        #pragma unroll
        for (int e = 0; e < NEXP; e++) {
            float v = Ls[t][e];
            if (v > best) { best = v; bi = e; }
        }
        Ls[t][bi] = -1.f;
        out[tok * TOPK + kk] = (float)bi;
        out[(long)ntok * TOPK + tok * TOPK + kk] = best;
        atomicAdd(&cntS[bi], 1u);
    }
    __syncthreads();
    if (cntS[t]) atomicAdd(&g_cnt[t], cntS[t]);
}

__global__ void finalize_kernel(float* __restrict__ aux, int nblocks, float ntokf) {
    int e = threadIdx.x;   // 64 threads
    float s = 0.f;
    for (int b = 0; b < nblocks; b++) s += g_pi_part[b][e];
    float Pi = s / ntokf;
    float ce = (float)g_cnt[e] / (ntokf * (float)TOPK);
    float v = Pi * ce * (float)NEXP;
    __shared__ float red[2];
    #pragma unroll
    for (int off = 16; off; off >>= 1)
        v += __shfl_xor_sync(0xffffffffu, v, off);
    if ((e & 31) == 0) red[e >> 5] = v;
    __syncthreads();
    if (e == 0) aux[0] = (red[0] + red[1]) * 0.01f;
}

extern "C" void kernel_launch(void* const* d_in, const int* in_sizes, int n_in,
                              void* d_out, int out_size) {
    const float* x = (const float*)d_in[0];
    const float* w = (const float*)d_in[1];
    float* out = (float*)d_out;
    int ntok = in_sizes[0] / EMBED;        // 32768
    int nblocks = ntok / TOKS;             // 512
    prep_kernel<<<(NEXP * EMBED) / 256, 256>>>(w);
    gate_kernel<<<nblocks, TPB>>>(x, out, ntok);
    finalize_kernel<<<1, 64>>>(out + (long)ntok * 2 * TOPK, nblocks, (float)ntok);
}

// round 7
// speedup vs baseline: 1.0900x; 1.0071x over previous
#include <cuda_runtime.h>
#include <math.h>

#define EMBED   2048
#define NEXP    64
#define TOPK    8
#define KC      16                 // K-chunk
#define NCHUNK  (EMBED / KC)       // 128
#define TPB     128                // 4 warps: (token-group, expert-half)
#define TOKS    128                // tokens per CTA
#define NBLK    256

typedef unsigned long long u64;

__device__ float        g_wt[EMBED * NEXP];   // W transposed: [k][e]
__device__ float        g_pi_part[NBLK][NEXP];
__device__ unsigned int g_cnt[NEXP];

// One-shot per launch: transpose W into g_wt, zero counters.
__global__ void prep_kernel(const float* __restrict__ w) {
    int idx = blockIdx.x * blockDim.x + threadIdx.x;   // e*2048 + k
    int e = idx >> 11, k = idx & 2047;
    g_wt[k * NEXP + e] = w[idx];
    if (idx < NEXP) g_cnt[idx] = 0u;
}

__device__ __forceinline__ u64 ffma2(u64 a, u64 b, u64 c) {
    u64 d;
    asm("fma.rn.f32x2 %0, %1, %2, %3;" : "=l"(d) : "l"(a), "l"(b), "l"(c));
    return d;
}
__device__ __forceinline__ u64 pack2(float f) {
    u64 d;
    asm("mov.b64 %0, {%1, %1};" : "=l"(d) : "f"(f));
    return d;
}
__device__ __forceinline__ void lds_v2(u64& a, u64& b, unsigned addr) {
    asm volatile("ld.shared.v2.b64 {%0, %1}, [%2];" : "=l"(a), "=l"(b) : "r"(addr));
}
__device__ __forceinline__ void cp_async16(unsigned saddr, const void* gaddr) {
    asm volatile("cp.async.ca.shared.global [%0], [%1], 16;" :: "r"(saddr), "l"(gaddr));
}
__device__ __forceinline__ void cp_commit() { asm volatile("cp.async.commit_group;"); }
__device__ __forceinline__ void cp_wait1()  { asm volatile("cp.async.wait_group 1;" ::: "memory"); }
__device__ __forceinline__ void cp_wait0()  { asm volatile("cp.async.wait_group 0;" ::: "memory"); }

__device__ __forceinline__ void load16(float (&d)[16], const float* p) {
    #pragma unroll
    for (int i = 0; i < 4; i++) {
        float4 v = *(const float4*)(p + i * 4);
        d[i * 4 + 0] = v.x; d[i * 4 + 1] = v.y; d[i * 4 + 2] = v.z; d[i * 4 + 3] = v.w;
    }
}

__global__ void __launch_bounds__(TPB) gate_kernel(
    const float* __restrict__ x, float* __restrict__ out, int ntok)
{
    __shared__ __align__(16) float wbuf[3][KC * NEXP];   // 3 x 4KB Wt ring
    __shared__ float Ls[TOKS][NEXP + 1];
    __shared__ unsigned int cntS[NEXP];

    const int t   = threadIdx.x;          // 0..127
    const int l   = t & 31;               // lane
    const int wid = t >> 5;               // warp 0..3
    const int eh  = wid & 1;              // expert half
    const int tg  = wid >> 1;             // token group 0/1
    const int e0  = eh * 32;
    const int row0 = tg * 64 + 2 * l;     // local token rows row0, row0+1
    const long tokA = (long)blockIdx.x * TOKS + row0;
    const float* xr0 = x + tokA * EMBED;
    const float* xr1 = xr0 + EMBED;
    if (t < NEXP) cntS[t] = 0u;

    u64 acc0[16], acc1[16];               // 16 expert-pairs x 2 tokens
    #pragma unroll
    for (int m = 0; m < 16; m++) { acc0[m] = 0ULL; acc1[m] = 0ULL; }

    const unsigned wb0 = (unsigned)__cvta_generic_to_shared(&wbuf[0][0]);

    // stage Wt chunk 0 into ring slot 0 (128 threads x 2 x 16B = 4KB)
    #pragma unroll
    for (int j = 0; j < 2; j++) {
        int f = t + j * TPB;
        cp_async16(wb0 + f * 16, g_wt + f * 4);
    }
    cp_commit();

    float xa0[16], xa1[16], xn0[16], xn1[16];
    load16(xa0, xr0); load16(xa1, xr1);

    int rd = 0, wr = 1;
    for (int c = 0; c < NCHUNK; c++) {
        if (c + 1 < NCHUNK) {
            unsigned dst = wb0 + wr * (KC * NEXP * 4);
            const float* src = g_wt + (c + 1) * (KC * NEXP);
            #pragma unroll
            for (int j = 0; j < 2; j++) {
                int f = t + j * TPB;
                cp_async16(dst + f * 16, src + f * 4);
            }
            cp_commit();
            load16(xn0, xr0 + (c + 1) * KC);
            load16(xn1, xr1 + (c + 1) * KC);
            cp_wait1();
        } else {
            cp_wait0();
        }
        __syncthreads();

        const unsigned base = wb0 + rd * (KC * NEXP * 4) + e0 * 4;
        #pragma unroll
        for (int k = 0; k < KC; k++) {
            u64 a0 = pack2(xa0[k]);
            u64 a1 = pack2(xa1[k]);
            #pragma unroll
            for (int m = 0; m < 8; m++) {
                u64 b0, b1;
                lds_v2(b0, b1, base + k * (NEXP * 4) + m * 16);
                acc0[2 * m]     = ffma2(a0, b0, acc0[2 * m]);
                acc0[2 * m + 1] = ffma2(a0, b1, acc0[2 * m + 1]);
                acc1[2 * m]     = ffma2(a1, b0, acc1[2 * m]);
                acc1[2 * m + 1] = ffma2(a1, b1, acc1[2 * m + 1]);
            }
        }
        if (c + 1 < NCHUNK) {
            #pragma unroll
            for (int i = 0; i < 16; i++) {
                xa0[i] = xn0[i]; xa1[i] = xn1[i];
            }
        }
        rd = (rd + 1) % 3; wr = (wr + 1) % 3;
    }

    // ---- logits -> smem (bitwise same values as prior passing rounds) ----
    #pragma unroll
    for (int m = 0; m < 16; m++) {
        unsigned lo, hi;
        asm("mov.b64 {%0, %1}, %2;" : "=r"(lo), "=r"(hi) : "l"(acc0[m]));
        Ls[row0][e0 + 2 * m]     = __uint_as_float(lo);
        Ls[row0][e0 + 2 * m + 1] = __uint_as_float(hi);
        asm("mov.b64 {%0, %1}, %2;" : "=r"(lo), "=r"(hi) : "l"(acc1[m]));
        Ls[row0 + 1][e0 + 2 * m]     = __uint_as_float(lo);
        Ls[row0 + 1][e0 + 2 * m + 1] = __uint_as_float(hi);
    }
    __syncthreads();

    // ---- softmax: thread t -> token row t; numerics identical ----
    {
        float lg[NEXP];
        #pragma unroll
        for (int e = 0; e < NEXP; e++) lg[e] = Ls[t][e];
        float mx = lg[0];
        #pragma unroll
        for (int e = 1; e < NEXP; e++) mx = fmaxf(mx, lg[e]);
        float ex[NEXP];
        #pragma unroll
        for (int e = 0; e < NEXP; e++) ex[e] = expf(lg[e] - mx);
        float v[32];
        #pragma unroll
        for (int j = 0; j < 32; j++) v[j] = ex[j] + ex[j + 32];
        #pragma unroll
        for (int off = 16; off >= 1; off >>= 1) {
            float nv[32];
            #pragma unroll
            for (int j = 0; j < 32; j++) nv[j] = v[j] + v[j ^ off];
            #pragma unroll
            for (int j = 0; j < 32; j++) v[j] = nv[j];
        }
        float s = v[0];
        __syncthreads();   // all logit reads done before overwrite
        #pragma unroll
        for (int e = 0; e < NEXP; e++) Ls[t][e] = ex[e] / s;
    }
    __syncthreads();

    // per-CTA Pi partials (rows ascending = tokens ascending: same global order)
    if (t < NEXP) {
        float s1 = 0.f;
        #pragma unroll
        for (int r = 0; r < TOKS; r++) s1 += Ls[r][t];
        g_pi_part[blockIdx.x][t] = s1;
    }
    __syncthreads();

    // top-8: ascending scan, strict > => lowest index wins ties
    const long tok = (long)blockIdx.x * TOKS + t;
    #pragma unroll 1
    for (int kk = 0; kk < TOPK; kk++) {
        float best = -1.f; int bi = 0;
        #pragma unroll
        for (int e = 0; e < NEXP; e++) {
            float v = Ls[t][e];
            if (v > best) { best = v; bi = e; }
        }
        Ls[t][bi] = -1.f;
        out[tok * TOPK + kk] = (float)bi;
        out[(long)ntok * TOPK + tok * TOPK + kk] = best;
        atomicAdd(&cntS[bi], 1u);
    }
    __syncthreads();
    if (t < NEXP && cntS[t]) atomicAdd(&g_cnt[t], cntS[t]);
}

__global__ void finalize_kernel(float* __restrict__ aux, int nblocks, float ntokf) {
    int e = threadIdx.x;   // 64 threads
    float s = 0.f;
    for (int b = 0; b < nblocks; b++) s += g_pi_part[b][e];
    float Pi = s / ntokf;
    float ce = (float)g_cnt[e] / (ntokf * (float)TOPK);
    float v = Pi * ce * (float)NEXP;
    __shared__ float red[2];
    #pragma unroll
    for (int off = 16; off; off >>= 1)
        v += __shfl_xor_sync(0xffffffffu, v, off);
    if ((e & 31) == 0) red[e >> 5] = v;
    __syncthreads();
    if (e == 0) aux[0] = (red[0] + red[1]) * 0.01f;
}

extern "C" void kernel_launch(void* const* d_in, const int* in_sizes, int n_in,
                              void* d_out, int out_size) {
    const float* x = (const float*)d_in[0];
    const float* w = (const float*)d_in[1];
    float* out = (float*)d_out;
    int ntok = in_sizes[0] / EMBED;        // 32768
    int nblocks = ntok / TOKS;             // 256
    prep_kernel<<<(NEXP * EMBED) / 256, 256>>>(w);
    gate_kernel<<<nblocks, TPB>>>(x, out, ntok);
    finalize_kernel<<<1, 64>>>(out + (long)ntok * 2 * TOPK, nblocks, (float)ntok);
}